// round 7
// baseline (speedup 1.0000x reference)
#include <cuda_runtime.h>
#include <cstdint>

#define NHEAD  8
#define NTOK   49
#define BWIN   1024
#define MROWS  50176
#define NW1    196608             // 256*768
#define NW2    65536              // 256*256

__device__ float g_q[BWIN * NHEAD * NTOK * 32];
__device__ float g_k[BWIN * NHEAD * NTOK * 32];
__device__ float g_v[BWIN * NHEAD * NTOK * 32];
__device__ float g_ao[MROWS * 256];
__device__ float g_wqkvT[768 * 256];      // [N][K], tf32-rounded
__device__ float g_wprojT[256 * 256];     // [N][K], tf32-rounded

__device__ __forceinline__ unsigned f2tf(float f) {
    unsigned u;
    asm("cvt.rna.tf32.f32 %0, %1;" : "=r"(u) : "f"(f));
    return u;
}
__device__ __forceinline__ float rtf(float f) { return __uint_as_float(f2tf(f)); }

__device__ __forceinline__ void mma8(float* c, const unsigned* a, const unsigned* b) {
    asm volatile(
        "mma.sync.aligned.m16n8k8.row.col.f32.tf32.tf32.f32 "
        "{%0,%1,%2,%3},{%4,%5,%6,%7},{%8,%9},{%0,%1,%2,%3};"
        : "+f"(c[0]), "+f"(c[1]), "+f"(c[2]), "+f"(c[3])
        : "r"(a[0]), "r"(a[1]), "r"(a[2]), "r"(a[3]), "r"(b[0]), "r"(b[1]));
}

#define LDSM4(R, ADDR)                                                        \
    asm volatile("ldmatrix.sync.aligned.m8n8.x4.shared.b16 {%0,%1,%2,%3}, [%4];" \
        : "=r"((R)[0]), "=r"((R)[1]), "=r"((R)[2]), "=r"((R)[3]) : "r"(ADDR))

__device__ __forceinline__ void cpa16(unsigned dst, const void* src) {
    asm volatile("cp.async.cg.shared.global [%0], [%1], 16;" :: "r"(dst), "l"(src));
}
__device__ __forceinline__ void cpa_commit() {
    asm volatile("cp.async.commit_group;");
}
template <int N>
__device__ __forceinline__ void cpa_wait() {
    asm volatile("cp.async.wait_group %0;" :: "n"(N));
}

// ============================================================
// Pre-pass: transpose + TF32-round both weight matrices.
// ============================================================
__global__ void __launch_bounds__(256) round_wT(
    const float* __restrict__ w1, const float* __restrict__ w2)
{
    int i = blockIdx.x * 256 + threadIdx.x;
    if (i < 768 * 256) {
        int n = i >> 8, k = i & 255;
        g_wqkvT[i] = rtf(w1[k * 768 + n]);
    } else {
        int j = i - 768 * 256;
        int n = j >> 8, k = j & 255;
        g_wprojT[j] = rtf(w2[k * 256 + n]);
    }
}

// ============================================================
// GEMM tiles: block 128x128, 8 warps (2m x 4n), warp 64x32,
// K-slice 32, 3-stage cp.async pipeline, LDSM fragment loads.
// smem: A[3][128][36] + B[3][128][36] floats = 110592 B.
// Both A and B smem are [row][k] with k contiguous, pad 36.
// ============================================================
#define A_ST 4608          // 128*36 floats
#define B_ST 4608
#define B_BASE 13824       // 3*A_ST
#define SMEM_BYTES 110592

// MODE 0: qkv (A gathered from query, B = g_wqkvT, scatter epilogue)
// MODE 1: proj (A = g_ao, B = g_wprojT, window-reverse + roll epilogue)
template <int MODE>
__global__ void __launch_bounds__(256) tc_gemm(
    const float* __restrict__ Aglob, const float* __restrict__ bias,
    float* __restrict__ out)
{
    extern __shared__ float sm[];
    __shared__ int rsrc[128];

    const int tid = threadIdx.x;
    const int m0 = blockIdx.x * 128;
    const int n0 = blockIdx.y * 128;

    if (MODE == 0 && tid < 128) {
        int m = m0 + tid;
        int win = m / 49, n = m - win * 49;
        int b = win >> 6, wy = (win >> 3) & 7, wx = win & 7;
        int iy = n / 7, ix = n - iy * 7;
        int y = wy * 7 + iy + 3; if (y >= 56) y -= 56;
        int x = wx * 7 + ix + 3; if (x >= 56) x -= 56;
        rsrc[tid] = ((b * 56 + y) * 56 + x) * 256;
    }
    __syncthreads();

    const unsigned sbase = (unsigned)__cvta_generic_to_shared(sm);
    const float* Asrc = (MODE == 0) ? Aglob : g_ao;
    const float* Wt   = (MODE == 0) ? g_wqkvT : g_wprojT;

    // cp.async assignments: 8 chunks per thread (4 A rows-halves, 4 B)
    int ar[4], ac[4], br[4], bc[4];
#pragma unroll
    for (int t = 0; t < 4; t++) {
        int id = tid + t * 256;
        ar[t] = id >> 3;  ac[t] = (id & 7) << 2;        // A: ids 0..1023
        br[t] = id >> 3;  bc[t] = (id & 7) << 2;        // B: ids 1024..2047 (same split)
    }

#define ISSUE(STG, K0)                                                        \
    {                                                                         \
        _Pragma("unroll") for (int t = 0; t < 4; t++)                         \
            cpa16(sbase + ((STG) * A_ST + ar[t] * 36 + ac[t]) * 4,            \
                  (MODE == 0) ? (Asrc + rsrc[ar[t]] + (K0) + ac[t])           \
                              : (Asrc + (m0 + ar[t]) * 256 + (K0) + ac[t]));  \
        _Pragma("unroll") for (int t = 0; t < 4; t++)                         \
            cpa16(sbase + (B_BASE + (STG) * B_ST + br[t] * 36 + bc[t]) * 4,   \
                  Wt + (n0 + br[t]) * 256 + (K0) + bc[t]);                    \
    }

    float acc[4][4][4];
#pragma unroll
    for (int i = 0; i < 4; i++)
#pragma unroll
        for (int j = 0; j < 4; j++)
#pragma unroll
            for (int l = 0; l < 4; l++) acc[i][j][l] = 0.f;

    const int warp = tid >> 5, lane = tid & 31;
    const int g = lane >> 2, tg = lane & 3;
    const int wm = warp >> 2, wn = warp & 3;

    // per-lane ldmatrix base offsets (bytes, within a stage)
    const int arow = (lane & 7) + ((lane >> 3) & 1) * 8;
    const int acol = (lane >> 4) * 4;
    unsigned a_off[4];
#pragma unroll
    for (int ma = 0; ma < 4; ma++)
        a_off[ma] = ((wm * 64 + ma * 16 + arow) * 36 + acol) * 4;

    const int brow = (lane & 7) + ((lane >> 4) & 1) * 8;
    const int bcol = ((lane >> 3) & 1) * 4;
    unsigned b_off[2];
#pragma unroll
    for (int j = 0; j < 2; j++)
        b_off[j] = (B_BASE + (wn * 32 + j * 16 + brow) * 36 + bcol) * 4;

    ISSUE(0, 0);  cpa_commit();
    ISSUE(1, 32); cpa_commit();
    cpa_wait<1>();
    __syncthreads();

    for (int it = 0; it < 8; it++) {
        const int stg = it - (it >= 6 ? 6 : (it >= 3 ? 3 : 0));   // it % 3
        const unsigned sa = sbase + stg * A_ST * 4;
        const unsigned sb = sbase + stg * B_ST * 4;

#pragma unroll
        for (int ka = 0; ka < 4; ka++) {
            unsigned a[4][4], bq[2][4];
#pragma unroll
            for (int ma = 0; ma < 4; ma++)
                LDSM4(a[ma], sa + a_off[ma] + ka * 32);
#pragma unroll
            for (int j = 0; j < 2; j++)
                LDSM4(bq[j], sb + b_off[j] + ka * 32);
#pragma unroll
            for (int ma = 0; ma < 4; ma++)
#pragma unroll
                for (int na = 0; na < 4; na++)
                    mma8(acc[ma][na], a[ma], &bq[na >> 1][(na & 1) * 2]);
        }

        if (it + 2 < 8) {
            int ns = it + 2; ns -= (ns >= 6 ? 6 : (ns >= 3 ? 3 : 0));
            ISSUE(ns, (it + 2) * 32);
        }
        cpa_commit();
        cpa_wait<1>();
        __syncthreads();
    }
#undef ISSUE

    // -------- epilogue --------
    const float scale = 0.17677669529663687f;
#pragma unroll
    for (int ma = 0; ma < 4; ma++) {
#pragma unroll
        for (int rr = 0; rr < 2; rr++) {
            int r = m0 + wm * 64 + ma * 16 + g + rr * 8;
            int win = r / 49, n = r - win * 49;
            int obase = 0;
            if (MODE == 1) {
                int b = win >> 6, wy = (win >> 3) & 7, wx = win & 7;
                int iy = n / 7, ix = n - iy * 7;
                int y = wy * 7 + iy + 3; if (y >= 56) y -= 56;
                int x = wx * 7 + ix + 3; if (x >= 56) x -= 56;
                obase = ((b * 56 + y) * 56 + x) * 256;
            }
#pragma unroll
            for (int na = 0; na < 4; na++) {
                int c = n0 + wn * 32 + na * 8 + tg * 2;
                float v0 = acc[ma][na][rr * 2 + 0] + bias[c];
                float v1 = acc[ma][na][rr * 2 + 1] + bias[c + 1];
                if (MODE == 0) {
                    int part = c >> 8;
                    if (part == 0) { v0 *= scale; v1 *= scale; }
                    int hh = (c >> 5) & 7, d = c & 31;
                    float* dst = (part == 0) ? g_q : ((part == 1) ? g_k : g_v);
                    *(float2*)(dst + (((win << 3) + hh) * 49 + n) * 32 + d) =
                        make_float2(rtf(v0), rtf(v1));
                } else {
                    *(float2*)(out + obase + c) = make_float2(v0, v1);
                }
            }
        }
    }
}

// ============================================================
// Attention (unchanged from R5): block = (window, head).
// ============================================================
__global__ void __launch_bounds__(128) attn_kernel(const float* __restrict__ rbt)
{
    const int bx = blockIdx.x;
    const int win = bx >> 3, h = bx & 7;

    __shared__ unsigned As[64][36];
    __shared__ unsigned Ks[56][36];
    __shared__ unsigned Vs[56][36];
    __shared__ float    S[64][57];
    __shared__ float    biasH[169];
    __shared__ int      cnt[49];

    const int tid = threadIdx.x;
    const int warp = tid >> 5, lane = tid & 31;
    const int g = lane >> 2, tg = lane & 3;

    const int base = ((win * 8 + h) * 49) * 32;
    const float* qp = g_q + base;
    const float* kp = g_k + base;
    const float* vp = g_v + base;

    for (int i = tid; i < 392; i += 128) {
        int r = i >> 3, c = (i & 7) << 2;
        *(uint4*)&As[r][c] = ((const uint4*)qp)[i];
        *(uint4*)&Ks[r][c] = ((const uint4*)kp)[i];
        *(uint4*)&Vs[r][c] = ((const uint4*)vp)[i];
    }
    if (tid < 112) {
        int a = tid >> 3, c = (tid & 7) << 2;
        uint4 z = make_uint4(0u, 0u, 0u, 0u);
        if (a < 7) *(uint4*)&Ks[49 + a][c] = z;
        else       *(uint4*)&Vs[42 + a][c] = z;
    }
    for (int i = tid; i < 169; i += 128) biasH[i] = rbt[i * 8 + h];
    if (tid < 49) {
        int iy = tid / 7, ix = tid - iy * 7;
        int wy = (win >> 3) & 7, wx = win & 7;
        int y = wy * 7 + iy, x = wx * 7 + ix;
        int ry = y < 49 ? 0 : (y < 53 ? 1 : 2);
        int rx = x < 49 ? 0 : (x < 53 ? 1 : 2);
        cnt[tid] = ry * 3 + rx;
    }
    __syncthreads();

    const int r0 = warp * 16 + g;
    float invs[2];

    int cjy[7][2], cjx[7][2];
#pragma unroll
    for (int na = 0; na < 7; na++)
#pragma unroll
        for (int e = 0; e < 2; e++) {
            int col = na * 8 + 2 * tg + e;
            cjy[na][e] = (col < 49) ? col / 7 : -1;
            cjx[na][e] = col - cjy[na][e] * 7;
        }

    {
        float acc[7][4];
#pragma unroll
        for (int na = 0; na < 7; na++)
#pragma unroll
            for (int l = 0; l < 4; l++) acc[na][l] = 0.f;

#pragma unroll
        for (int ka = 0; ka < 4; ka++) {
            unsigned a[4];
            a[0] = As[r0][ka * 8 + tg];
            a[1] = As[r0 + 8][ka * 8 + tg];
            a[2] = As[r0][ka * 8 + tg + 4];
            a[3] = As[r0 + 8][ka * 8 + tg + 4];
#pragma unroll
            for (int na = 0; na < 7; na++) {
                unsigned b[2] = { Ks[na * 8 + g][ka * 8 + tg],
                                  Ks[na * 8 + g][ka * 8 + tg + 4] };
                mma8(acc[na], a, b);
            }
        }

#pragma unroll
        for (int half = 0; half < 2; half++) {
            int row = r0 + half * 8;
            bool rok = row < 49;
            int iy = 0, ix = 0, ci = 0;
            if (rok) { iy = row / 7; ix = row - iy * 7; ci = cnt[row]; }
            float esum = 0.f;
#pragma unroll
            for (int na = 0; na < 7; na++) {
#pragma unroll
                for (int e = 0; e < 2; e++) {
                    int col = na * 8 + 2 * tg + e;
                    float ev = 0.f;
                    if (rok && cjy[na][e] >= 0) {
                        float v = acc[na][half * 2 + e]
                                + biasH[(iy - cjy[na][e] + 6) * 13
                                        + (ix - cjx[na][e] + 6)];
                        if (cnt[col] != ci) v -= 100.f;
                        ev = __expf(v);
                    }
                    S[row][col] = __uint_as_float(f2tf(ev));
                    esum += ev;
                }
            }
            esum += __shfl_xor_sync(0xffffffffu, esum, 1);
            esum += __shfl_xor_sync(0xffffffffu, esum, 2);
            invs[half] = 1.f / esum;
        }
    }
    __syncwarp();

    {
        float o[4][4];
#pragma unroll
        for (int na = 0; na < 4; na++)
#pragma unroll
            for (int l = 0; l < 4; l++) o[na][l] = 0.f;

#pragma unroll
        for (int ka = 0; ka < 7; ka++) {
            unsigned a[4];
            a[0] = __float_as_uint(S[r0][ka * 8 + tg]);
            a[1] = __float_as_uint(S[r0 + 8][ka * 8 + tg]);
            a[2] = __float_as_uint(S[r0][ka * 8 + tg + 4]);
            a[3] = __float_as_uint(S[r0 + 8][ka * 8 + tg + 4]);
#pragma unroll
            for (int na = 0; na < 4; na++) {
                unsigned b[2] = { Vs[ka * 8 + tg][na * 8 + g],
                                  Vs[ka * 8 + tg + 4][na * 8 + g] };
                mma8(o[na], a, b);
            }
        }

#pragma unroll
        for (int half = 0; half < 2; half++) {
            int row = r0 + half * 8;
            if (row < 49) {
                float s = invs[half];
                float* op = g_ao + (win * 49 + row) * 256 + h * 32;
#pragma unroll
                for (int na = 0; na < 4; na++) {
                    int col = na * 8 + 2 * tg;
                    *(float2*)(op + col) =
                        make_float2(rtf(o[na][half * 2 + 0] * s),
                                    rtf(o[na][half * 2 + 1] * s));
                }
            }
        }
    }
}

// ============================================================
extern "C" void kernel_launch(void* const* d_in, const int* in_sizes, int n_in,
                              void* d_out, int out_size)
{
    const float* query  = (const float*)d_in[0];
    const float* w_qkv  = (const float*)d_in[1];
    const float* b_qkv  = (const float*)d_in[2];
    const float* w_proj = (const float*)d_in[3];
    const float* b_proj = (const float*)d_in[4];
    const float* rbt    = (const float*)d_in[5];
    float* out = (float*)d_out;

    static int attr_done = 0;
    if (!attr_done) {
        cudaFuncSetAttribute(tc_gemm<0>,
            cudaFuncAttributeMaxDynamicSharedMemorySize, SMEM_BYTES);
        cudaFuncSetAttribute(tc_gemm<1>,
            cudaFuncAttributeMaxDynamicSharedMemorySize, SMEM_BYTES);
        attr_done = 1;
    }

    round_wT<<<1024, 256>>>(w_qkv, w_proj);

    dim3 g1(392, 6);
    tc_gemm<0><<<g1, 256, SMEM_BYTES>>>(query, b_qkv, nullptr);

    attn_kernel<<<8192, 128>>>(rbt);

    dim3 g3(392, 2);
    tc_gemm<1><<<g3, 256, SMEM_BYTES>>>(nullptr, b_proj, out);
}

// round 9
// speedup vs baseline: 1.6753x; 1.6753x over previous
#include <cuda_runtime.h>
#include <cuda_fp16.h>
#include <cstdint>

#define NHEAD  8
#define NTOK   49
#define BWIN   1024
#define MROWS  50176
#define NQ     12845056           // 16*56*56*256

__device__ float  g_q[BWIN * NHEAD * NTOK * 32];
__device__ float  g_k[BWIN * NHEAD * NTOK * 32];
__device__ float  g_v[BWIN * NHEAD * NTOK * 32];
__device__ __half g_qh[NQ];               // fp16 query, natural layout
__device__ __half g_aoh[MROWS * 256];     // fp16 attn output
__device__ __half g_whq[768 * 256];       // w_qkv^T [n][k] fp16
__device__ __half g_whp[256 * 256];       // w_proj^T [n][k] fp16

__device__ __forceinline__ unsigned f2tf(float f) {
    unsigned u;
    asm("cvt.rna.tf32.f32 %0, %1;" : "=r"(u) : "f"(f));
    return u;
}
__device__ __forceinline__ float rtf(float f) { return __uint_as_float(f2tf(f)); }

// tf32 m16n8k8 (attention only)
__device__ __forceinline__ void mma8(float* c, const unsigned* a, const unsigned* b) {
    asm volatile(
        "mma.sync.aligned.m16n8k8.row.col.f32.tf32.tf32.f32 "
        "{%0,%1,%2,%3},{%4,%5,%6,%7},{%8,%9},{%0,%1,%2,%3};"
        : "+f"(c[0]), "+f"(c[1]), "+f"(c[2]), "+f"(c[3])
        : "r"(a[0]), "r"(a[1]), "r"(a[2]), "r"(a[3]), "r"(b[0]), "r"(b[1]));
}
// fp16 m16n8k16 (GEMMs)
__device__ __forceinline__ void mma16(float* c, const unsigned* a, const unsigned* b) {
    asm volatile(
        "mma.sync.aligned.m16n8k16.row.col.f32.f16.f16.f32 "
        "{%0,%1,%2,%3},{%4,%5,%6,%7},{%8,%9},{%0,%1,%2,%3};"
        : "+f"(c[0]), "+f"(c[1]), "+f"(c[2]), "+f"(c[3])
        : "r"(a[0]), "r"(a[1]), "r"(a[2]), "r"(a[3]), "r"(b[0]), "r"(b[1]));
}

__device__ __forceinline__ void cpa16(unsigned dst, const void* src) {
    asm volatile("cp.async.cg.shared.global [%0], [%1], 16;" :: "r"(dst), "l"(src));
}
__device__ __forceinline__ void cpa_commit() {
    asm volatile("cp.async.commit_group;");
}
template <int N>
__device__ __forceinline__ void cpa_wait() {
    asm volatile("cp.async.wait_group %0;" :: "n"(N));
}

// ============================================================
// Pre-pass A: query fp32 -> fp16 (vectorized)
// ============================================================
__global__ void __launch_bounds__(256) conv_q(const float4* __restrict__ q)
{
    int i = blockIdx.x * 256 + threadIdx.x;   // i < NQ/4
    float4 v = q[i];
    half2 lo = __floats2half2_rn(v.x, v.y);
    half2 hi = __floats2half2_rn(v.z, v.w);
    uint2 pk;
    pk.x = *(unsigned*)&lo;
    pk.y = *(unsigned*)&hi;
    ((uint2*)g_qh)[i] = pk;
}

// ============================================================
// Pre-pass B: transpose + fp16 both weights. [k][n] -> [n][k]
// ============================================================
__global__ void __launch_bounds__(256) conv_w(
    const float* __restrict__ w1, const float* __restrict__ w2)
{
    int i = blockIdx.x * 256 + threadIdx.x;
    if (i < 768 * 256) {
        int n = i >> 8, k = i & 255;
        g_whq[i] = __float2half_rn(w1[k * 768 + n]);
    } else {
        int j = i - 768 * 256;
        int n = j >> 8, k = j & 255;
        g_whp[j] = __float2half_rn(w2[k * 256 + n]);
    }
}

// ============================================================
// FP16 GEMM: block 128x128, 8 warps (2m x 4n), warp 64x32,
// K-chunk 32 (2 x k16 mma steps), 3-stage cp.async pipeline.
// smem rows: 40 halves (20 words) -> conflict-free, 16B-aligned.
// A and B both [row][k] (B rows are n, from transposed weights).
// ============================================================
#define A_ST 2560            // words per stage (128 rows x 20 words)
#define B_BASE 7680          // 3 * A_ST
#define SMEM_BYTES 61440     // 6 * 2560 * 4

// MODE 0: qkv (A = gathered g_qh, B = g_whq, scatter epilogue)
// MODE 1: proj (A = g_aoh, B = g_whp, window-reverse + roll epilogue)
template <int MODE>
__global__ void __launch_bounds__(256) hgemm(
    const float* __restrict__ bias, float* __restrict__ out)
{
    extern __shared__ unsigned sw[];
    __shared__ int rsrc[128];

    const int tid = threadIdx.x;
    const int m0 = blockIdx.x * 128;
    const int n0 = blockIdx.y * 128;

    if (MODE == 0 && tid < 128) {
        int m = m0 + tid;
        int win = m / 49, n = m - win * 49;
        int b = win >> 6, wy = (win >> 3) & 7, wx = win & 7;
        int iy = n / 7, ix = n - iy * 7;
        int y = wy * 7 + iy + 3; if (y >= 56) y -= 56;
        int x = wx * 7 + ix + 3; if (x >= 56) x -= 56;
        rsrc[tid] = ((b * 56 + y) * 56 + x) * 256;
    }
    __syncthreads();

    const unsigned sbase = (unsigned)__cvta_generic_to_shared(sw);
    const __half* Ah = (MODE == 0) ? g_qh : g_aoh;
    const __half* Bh = (MODE == 0) ? g_whq : g_whp;

    // cp.async: 2 A chunks + 2 B chunks per thread per stage (16B each)
    int ar[2], ac[2];
#pragma unroll
    for (int t = 0; t < 2; t++) {
        int id = tid + t * 256;            // 0..511
        ar[t] = id >> 2;  ac[t] = id & 3;  // row, 16B-chunk (8 halves)
    }

#define ISSUE(STG, K0)                                                        \
    {                                                                         \
        _Pragma("unroll") for (int t = 0; t < 2; t++)                         \
            cpa16(sbase + ((STG) * A_ST + ar[t] * 20 + ac[t] * 4) * 4,        \
                  (MODE == 0) ? (Ah + rsrc[ar[t]] + (K0) + ac[t] * 8)         \
                              : (Ah + (m0 + ar[t]) * 256 + (K0) + ac[t] * 8));\
        _Pragma("unroll") for (int t = 0; t < 2; t++)                         \
            cpa16(sbase + (B_BASE + (STG) * A_ST + ar[t] * 20 + ac[t] * 4) * 4,\
                  Bh + (n0 + ar[t]) * 256 + (K0) + ac[t] * 8);                \
    }

    float acc[4][4][4];
#pragma unroll
    for (int i = 0; i < 4; i++)
#pragma unroll
        for (int j = 0; j < 4; j++)
#pragma unroll
            for (int l = 0; l < 4; l++) acc[i][j][l] = 0.f;

    const int warp = tid >> 5, lane = tid & 31;
    const int g = lane >> 2, tg = lane & 3;
    const int wm = warp >> 2, wn = warp & 3;

    ISSUE(0, 0);  cpa_commit();
    ISSUE(1, 32); cpa_commit();
    cpa_wait<1>();
    __syncthreads();

    for (int it = 0; it < 8; it++) {
        const int stg = it - (it >= 6 ? 6 : (it >= 3 ? 3 : 0));   // it % 3
        const unsigned* As = sw + stg * A_ST;
        const unsigned* Bs = sw + B_BASE + stg * A_ST;

#pragma unroll
        for (int ka = 0; ka < 2; ka++) {       // two k16 steps per 32-chunk
            unsigned a[4][4], bb[4][2];
            const int kw = ka * 8;             // word offset of k16 step
#pragma unroll
            for (int ma = 0; ma < 4; ma++) {
                int r = wm * 64 + ma * 16 + g;
                a[ma][0] = As[r * 20 + kw + tg];
                a[ma][1] = As[(r + 8) * 20 + kw + tg];
                a[ma][2] = As[r * 20 + kw + tg + 4];
                a[ma][3] = As[(r + 8) * 20 + kw + tg + 4];
            }
#pragma unroll
            for (int na = 0; na < 4; na++) {
                int nr = wn * 32 + na * 8 + g;
                bb[na][0] = Bs[nr * 20 + kw + tg];
                bb[na][1] = Bs[nr * 20 + kw + tg + 4];
            }
#pragma unroll
            for (int ma = 0; ma < 4; ma++)
#pragma unroll
                for (int na = 0; na < 4; na++) mma16(acc[ma][na], a[ma], bb[na]);
        }

        if (it + 2 < 8) {
            int ns = it + 2; ns -= (ns >= 6 ? 6 : (ns >= 3 ? 3 : 0));
            ISSUE(ns, (it + 2) * 32);
        }
        cpa_commit();
        cpa_wait<1>();
        __syncthreads();
    }
#undef ISSUE

    // -------- epilogue (identical acc layout to R5) --------
    const float scale = 0.17677669529663687f;
#pragma unroll
    for (int ma = 0; ma < 4; ma++) {
#pragma unroll
        for (int rr = 0; rr < 2; rr++) {
            int r = m0 + wm * 64 + ma * 16 + g + rr * 8;
            int win = r / 49, n = r - win * 49;
            int obase = 0;
            if (MODE == 1) {
                int b = win >> 6, wy = (win >> 3) & 7, wx = win & 7;
                int iy = n / 7, ix = n - iy * 7;
                int y = wy * 7 + iy + 3; if (y >= 56) y -= 56;
                int x = wx * 7 + ix + 3; if (x >= 56) x -= 56;
                obase = ((b * 56 + y) * 56 + x) * 256;
            }
#pragma unroll
            for (int na = 0; na < 4; na++) {
                int c = n0 + wn * 32 + na * 8 + tg * 2;
                float v0 = acc[ma][na][rr * 2 + 0] + bias[c];
                float v1 = acc[ma][na][rr * 2 + 1] + bias[c + 1];
                if (MODE == 0) {
                    int part = c >> 8;
                    if (part == 0) { v0 *= scale; v1 *= scale; }
                    int hh = (c >> 5) & 7, d = c & 31;
                    float* dst = (part == 0) ? g_q : ((part == 1) ? g_k : g_v);
                    *(float2*)(dst + (((win << 3) + hh) * 49 + n) * 32 + d) =
                        make_float2(rtf(v0), rtf(v1));
                } else {
                    *(float2*)(out + obase + c) = make_float2(v0, v1);
                }
            }
        }
    }
}

// ============================================================
// Attention (R5, unchanged except fp16 output store).
// ============================================================
__global__ void __launch_bounds__(128) attn_kernel(const float* __restrict__ rbt)
{
    const int bx = blockIdx.x;
    const int win = bx >> 3, h = bx & 7;

    __shared__ unsigned As[64][36];
    __shared__ unsigned Ks[56][36];
    __shared__ unsigned Vs[56][36];
    __shared__ float    S[64][57];
    __shared__ float    biasH[169];
    __shared__ int      cnt[49];

    const int tid = threadIdx.x;
    const int warp = tid >> 5, lane = tid & 31;
    const int g = lane >> 2, tg = lane & 3;

    const int base = ((win * 8 + h) * 49) * 32;
    const float* qp = g_q + base;
    const float* kp = g_k + base;
    const float* vp = g_v + base;

    for (int i = tid; i < 392; i += 128) {
        int r = i >> 3, c = (i & 7) << 2;
        *(uint4*)&As[r][c] = ((const uint4*)qp)[i];
        *(uint4*)&Ks[r][c] = ((const uint4*)kp)[i];
        *(uint4*)&Vs[r][c] = ((const uint4*)vp)[i];
    }
    if (tid < 112) {
        int a = tid >> 3, c = (tid & 7) << 2;
        uint4 z = make_uint4(0u, 0u, 0u, 0u);
        if (a < 7) *(uint4*)&Ks[49 + a][c] = z;
        else       *(uint4*)&Vs[42 + a][c] = z;
    }
    for (int i = tid; i < 169; i += 128) biasH[i] = rbt[i * 8 + h];
    if (tid < 49) {
        int iy = tid / 7, ix = tid - iy * 7;
        int wy = (win >> 3) & 7, wx = win & 7;
        int y = wy * 7 + iy, x = wx * 7 + ix;
        int ry = y < 49 ? 0 : (y < 53 ? 1 : 2);
        int rx = x < 49 ? 0 : (x < 53 ? 1 : 2);
        cnt[tid] = ry * 3 + rx;
    }
    __syncthreads();

    const int r0 = warp * 16 + g;
    float invs[2];

    int cjy[7][2], cjx[7][2];
#pragma unroll
    for (int na = 0; na < 7; na++)
#pragma unroll
        for (int e = 0; e < 2; e++) {
            int col = na * 8 + 2 * tg + e;
            cjy[na][e] = (col < 49) ? col / 7 : -1;
            cjx[na][e] = col - cjy[na][e] * 7;
        }

    {
        float acc[7][4];
#pragma unroll
        for (int na = 0; na < 7; na++)
#pragma unroll
            for (int l = 0; l < 4; l++) acc[na][l] = 0.f;

#pragma unroll
        for (int ka = 0; ka < 4; ka++) {
            unsigned a[4];
            a[0] = As[r0][ka * 8 + tg];
            a[1] = As[r0 + 8][ka * 8 + tg];
            a[2] = As[r0][ka * 8 + tg + 4];
            a[3] = As[r0 + 8][ka * 8 + tg + 4];
#pragma unroll
            for (int na = 0; na < 7; na++) {
                unsigned b[2] = { Ks[na * 8 + g][ka * 8 + tg],
                                  Ks[na * 8 + g][ka * 8 + tg + 4] };
                mma8(acc[na], a, b);
            }
        }

#pragma unroll
        for (int half = 0; half < 2; half++) {
            int row = r0 + half * 8;
            bool rok = row < 49;
            int iy = 0, ix = 0, ci = 0;
            if (rok) { iy = row / 7; ix = row - iy * 7; ci = cnt[row]; }
            float esum = 0.f;
#pragma unroll
            for (int na = 0; na < 7; na++) {
#pragma unroll
                for (int e = 0; e < 2; e++) {
                    int col = na * 8 + 2 * tg + e;
                    float ev = 0.f;
                    if (rok && cjy[na][e] >= 0) {
                        float v = acc[na][half * 2 + e]
                                + biasH[(iy - cjy[na][e] + 6) * 13
                                        + (ix - cjx[na][e] + 6)];
                        if (cnt[col] != ci) v -= 100.f;
                        ev = __expf(v);
                    }
                    S[row][col] = __uint_as_float(f2tf(ev));
                    esum += ev;
                }
            }
            esum += __shfl_xor_sync(0xffffffffu, esum, 1);
            esum += __shfl_xor_sync(0xffffffffu, esum, 2);
            invs[half] = 1.f / esum;
        }
    }
    __syncwarp();

    {
        float o[4][4];
#pragma unroll
        for (int na = 0; na < 4; na++)
#pragma unroll
            for (int l = 0; l < 4; l++) o[na][l] = 0.f;

#pragma unroll
        for (int ka = 0; ka < 7; ka++) {
            unsigned a[4];
            a[0] = __float_as_uint(S[r0][ka * 8 + tg]);
            a[1] = __float_as_uint(S[r0 + 8][ka * 8 + tg]);
            a[2] = __float_as_uint(S[r0][ka * 8 + tg + 4]);
            a[3] = __float_as_uint(S[r0 + 8][ka * 8 + tg + 4]);
#pragma unroll
            for (int na = 0; na < 4; na++) {
                unsigned b[2] = { Vs[ka * 8 + tg][na * 8 + g],
                                  Vs[ka * 8 + tg + 4][na * 8 + g] };
                mma8(o[na], a, b);
            }
        }

#pragma unroll
        for (int half = 0; half < 2; half++) {
            int row = r0 + half * 8;
            if (row < 49) {
                float s = invs[half];
                __half* op = g_aoh + (win * 49 + row) * 256 + h * 32;
#pragma unroll
                for (int na = 0; na < 4; na++) {
                    int col = na * 8 + 2 * tg;
                    *(half2*)(op + col) =
                        __floats2half2_rn(o[na][half * 2 + 0] * s,
                                          o[na][half * 2 + 1] * s);
                }
            }
        }
    }
}

// ============================================================
extern "C" void kernel_launch(void* const* d_in, const int* in_sizes, int n_in,
                              void* d_out, int out_size)
{
    const float* query  = (const float*)d_in[0];
    const float* w_qkv  = (const float*)d_in[1];
    const float* b_qkv  = (const float*)d_in[2];
    const float* w_proj = (const float*)d_in[3];
    const float* b_proj = (const float*)d_in[4];
    const float* rbt    = (const float*)d_in[5];
    float* out = (float*)d_out;

    static int attr_done = 0;
    if (!attr_done) {
        cudaFuncSetAttribute(hgemm<0>,
            cudaFuncAttributeMaxDynamicSharedMemorySize, SMEM_BYTES);
        cudaFuncSetAttribute(hgemm<1>,
            cudaFuncAttributeMaxDynamicSharedMemorySize, SMEM_BYTES);
        attr_done = 1;
    }

    conv_q<<<12544, 256>>>((const float4*)query);
    conv_w<<<1024, 256>>>(w_qkv, w_proj);

    dim3 g1(392, 6);
    hgemm<0><<<g1, 256, SMEM_BYTES>>>(b_qkv, nullptr);

    attn_kernel<<<8192, 128>>>(rbt);

    dim3 g3(392, 2);
    hgemm<1><<<g3, 256, SMEM_BYTES>>>(b_proj, out);
}

// round 11
// speedup vs baseline: 2.0268x; 1.2098x over previous
#include <cuda_runtime.h>
#include <cuda_fp16.h>
#include <cstdint>

#define NHEAD  8
#define NTOK   49
#define BWIN   1024
#define MROWS  50176
#define NQ     12845056           // 16*56*56*256

__device__ __half g_qh[NQ];               // fp16 query (GEMM A), natural layout
__device__ __half g_aoh[MROWS * 256];     // fp16 attn output
__device__ __half g_whq[768 * 256];       // w_qkv^T [n][k] fp16
__device__ __half g_whp[256 * 256];       // w_proj^T [n][k] fp16
__device__ __half g_qa[BWIN * NHEAD * NTOK * 32];   // attn Q (pre-scaled)
__device__ __half g_ka[BWIN * NHEAD * NTOK * 32];   // attn K
__device__ __half g_va[BWIN * NHEAD * NTOK * 32];   // attn V

// fp16 m16n8k16
__device__ __forceinline__ void mma16(float* c, const unsigned* a, const unsigned* b) {
    asm volatile(
        "mma.sync.aligned.m16n8k16.row.col.f32.f16.f16.f32 "
        "{%0,%1,%2,%3},{%4,%5,%6,%7},{%8,%9},{%0,%1,%2,%3};"
        : "+f"(c[0]), "+f"(c[1]), "+f"(c[2]), "+f"(c[3])
        : "r"(a[0]), "r"(a[1]), "r"(a[2]), "r"(a[3]), "r"(b[0]), "r"(b[1]));
}

__device__ __forceinline__ void cpa16(unsigned dst, const void* src) {
    asm volatile("cp.async.cg.shared.global [%0], [%1], 16;" :: "r"(dst), "l"(src));
}
__device__ __forceinline__ void cpa_commit() {
    asm volatile("cp.async.commit_group;");
}
template <int N>
__device__ __forceinline__ void cpa_wait() {
    asm volatile("cp.async.wait_group %0;" :: "n"(N));
}

// ============================================================
// Pre-pass A: query fp32 -> fp16 (vectorized)
// ============================================================
__global__ void __launch_bounds__(256) conv_q(const float4* __restrict__ q)
{
    int i = blockIdx.x * 256 + threadIdx.x;   // i < NQ/4
    float4 v = q[i];
    half2 lo = __floats2half2_rn(v.x, v.y);
    half2 hi = __floats2half2_rn(v.z, v.w);
    uint2 pk;
    pk.x = *(unsigned*)&lo;
    pk.y = *(unsigned*)&hi;
    ((uint2*)g_qh)[i] = pk;
}

// ============================================================
// Pre-pass B: transpose + fp16 both weights. [k][n] -> [n][k]
// ============================================================
__global__ void __launch_bounds__(256) conv_w(
    const float* __restrict__ w1, const float* __restrict__ w2)
{
    int i = blockIdx.x * 256 + threadIdx.x;
    if (i < 768 * 256) {
        int n = i >> 8, k = i & 255;
        g_whq[i] = __float2half_rn(w1[k * 768 + n]);
    } else {
        int j = i - 768 * 256;
        int n = j >> 8, k = j & 255;
        g_whp[j] = __float2half_rn(w2[k * 256 + n]);
    }
}

// ============================================================
// FP16 GEMM (same as R9): block 128x128, 8 warps, warp 64x32,
// K-chunk 32, 3-stage cp.async pipeline.
// ============================================================
#define A_ST 2560
#define B_BASE 7680
#define SMEM_BYTES 61440

template <int MODE>
__global__ void __launch_bounds__(256) hgemm(
    const float* __restrict__ bias, float* __restrict__ out)
{
    extern __shared__ unsigned sw[];
    __shared__ int rsrc[128];

    const int tid = threadIdx.x;
    const int m0 = blockIdx.x * 128;
    const int n0 = blockIdx.y * 128;

    if (MODE == 0 && tid < 128) {
        int m = m0 + tid;
        int win = m / 49, n = m - win * 49;
        int b = win >> 6, wy = (win >> 3) & 7, wx = win & 7;
        int iy = n / 7, ix = n - iy * 7;
        int y = wy * 7 + iy + 3; if (y >= 56) y -= 56;
        int x = wx * 7 + ix + 3; if (x >= 56) x -= 56;
        rsrc[tid] = ((b * 56 + y) * 56 + x) * 256;
    }
    __syncthreads();

    const unsigned sbase = (unsigned)__cvta_generic_to_shared(sw);
    const __half* Ah = (MODE == 0) ? g_qh : g_aoh;
    const __half* Bh = (MODE == 0) ? g_whq : g_whp;

    int ar[2], ac[2];
#pragma unroll
    for (int t = 0; t < 2; t++) {
        int id = tid + t * 256;
        ar[t] = id >> 2;  ac[t] = id & 3;
    }

#define ISSUE(STG, K0)                                                        \
    {                                                                         \
        _Pragma("unroll") for (int t = 0; t < 2; t++)                         \
            cpa16(sbase + ((STG) * A_ST + ar[t] * 20 + ac[t] * 4) * 4,        \
                  (MODE == 0) ? (Ah + rsrc[ar[t]] + (K0) + ac[t] * 8)         \
                              : (Ah + (m0 + ar[t]) * 256 + (K0) + ac[t] * 8));\
        _Pragma("unroll") for (int t = 0; t < 2; t++)                         \
            cpa16(sbase + (B_BASE + (STG) * A_ST + ar[t] * 20 + ac[t] * 4) * 4,\
                  Bh + (n0 + ar[t]) * 256 + (K0) + ac[t] * 8);                \
    }

    float acc[4][4][4];
#pragma unroll
    for (int i = 0; i < 4; i++)
#pragma unroll
        for (int j = 0; j < 4; j++)
#pragma unroll
            for (int l = 0; l < 4; l++) acc[i][j][l] = 0.f;

    const int warp = tid >> 5, lane = tid & 31;
    const int g = lane >> 2, tg = lane & 3;
    const int wm = warp >> 2, wn = warp & 3;

    ISSUE(0, 0);  cpa_commit();
    ISSUE(1, 32); cpa_commit();
    cpa_wait<1>();
    __syncthreads();

    for (int it = 0; it < 8; it++) {
        const int stg = it - (it >= 6 ? 6 : (it >= 3 ? 3 : 0));
        const unsigned* As = sw + stg * A_ST;
        const unsigned* Bs = sw + B_BASE + stg * A_ST;

#pragma unroll
        for (int ka = 0; ka < 2; ka++) {
            unsigned a[4][4], bb[4][2];
            const int kw = ka * 8;
#pragma unroll
            for (int ma = 0; ma < 4; ma++) {
                int r = wm * 64 + ma * 16 + g;
                a[ma][0] = As[r * 20 + kw + tg];
                a[ma][1] = As[(r + 8) * 20 + kw + tg];
                a[ma][2] = As[r * 20 + kw + tg + 4];
                a[ma][3] = As[(r + 8) * 20 + kw + tg + 4];
            }
#pragma unroll
            for (int na = 0; na < 4; na++) {
                int nr = wn * 32 + na * 8 + g;
                bb[na][0] = Bs[nr * 20 + kw + tg];
                bb[na][1] = Bs[nr * 20 + kw + tg + 4];
            }
#pragma unroll
            for (int ma = 0; ma < 4; ma++)
#pragma unroll
                for (int na = 0; na < 4; na++) mma16(acc[ma][na], a[ma], bb[na]);
        }

        if (it + 2 < 8) {
            int ns = it + 2; ns -= (ns >= 6 ? 6 : (ns >= 3 ? 3 : 0));
            ISSUE(ns, (it + 2) * 32);
        }
        cpa_commit();
        cpa_wait<1>();
        __syncthreads();
    }
#undef ISSUE

    const float scale = 0.17677669529663687f;
#pragma unroll
    for (int ma = 0; ma < 4; ma++) {
#pragma unroll
        for (int rr = 0; rr < 2; rr++) {
            int r = m0 + wm * 64 + ma * 16 + g + rr * 8;
            int win = r / 49, n = r - win * 49;
            int obase = 0;
            if (MODE == 1) {
                int b = win >> 6, wy = (win >> 3) & 7, wx = win & 7;
                int iy = n / 7, ix = n - iy * 7;
                int y = wy * 7 + iy + 3; if (y >= 56) y -= 56;
                int x = wx * 7 + ix + 3; if (x >= 56) x -= 56;
                obase = ((b * 56 + y) * 56 + x) * 256;
            }
#pragma unroll
            for (int na = 0; na < 4; na++) {
                int c = n0 + wn * 32 + na * 8 + tg * 2;
                float v0 = acc[ma][na][rr * 2 + 0] + bias[c];
                float v1 = acc[ma][na][rr * 2 + 1] + bias[c + 1];
                if (MODE == 0) {
                    int part = c >> 8;
                    if (part == 0) { v0 *= scale; v1 *= scale; }
                    int hh = (c >> 5) & 7, d = c & 31;
                    __half* dst = (part == 0) ? g_qa : ((part == 1) ? g_ka : g_va);
                    *(half2*)(dst + (((win << 3) + hh) * 49 + n) * 32 + d) =
                        __floats2half2_rn(v0, v1);
                } else {
                    *(float2*)(out + obase + c) = make_float2(v0, v1);
                }
            }
        }
    }
}

// ============================================================
// FP16 attention: block = (window, head), 128 threads, 4 warps.
// S = QK^T: m16n8k16, K natural [tok][d] gives B frags directly.
// V transposed in smem: Vt[d][tok], stride 72 halves (36 words)
// so the full k=64 token range lives inside each row; rows
// zeroed first (word stores), then transpose fills tokens 0-48.
// ============================================================
__global__ void __launch_bounds__(128) attn_kernel(const float* __restrict__ rbt)
{
    const int bx = blockIdx.x;
    const int win = bx >> 3, h = bx & 7;

    __shared__ unsigned Qs[64 * 20];     // rows 49-63 garbage (discarded)
    __shared__ unsigned Ks[56 * 20];     // rows 49-55 garbage (cols masked)
    __shared__ __half   Vt[32 * 72];     // [d][tok], stride 72 halves
    __shared__ unsigned Pw[64 * 36];     // P fp16, stride 36 words
    __shared__ float    biasH[169];
    __shared__ int      cnt[49];

    const int tid = threadIdx.x;
    const int warp = tid >> 5, lane = tid & 31;
    const int g = lane >> 2, tg = lane & 3;

    const int base = ((win * 8 + h) * 49) * 32;
    const __half* qp = g_qa + base;
    const __half* kp = g_ka + base;
    const __half* vp = g_va + base;

    // phase 0: zero all of Vt (32*36 = 1152 words)
    for (int i = tid; i < 1152; i += 128) ((unsigned*)Vt)[i] = 0u;
    __syncthreads();

    // phase 1: loads
    for (int i = tid; i < 196; i += 128) {
        int row = i >> 2, q = i & 3;
        *(uint4*)&Qs[row * 20 + q * 4] = ((const uint4*)qp)[i];
        *(uint4*)&Ks[row * 20 + q * 4] = ((const uint4*)kp)[i];
    }
    // V: load + transpose to Vt[d][tok] (tokens 0-48; rest stays 0)
    for (int i = tid; i < 196; i += 128) {
        int j = i >> 2, d0 = (i & 3) * 8;
        uint4 v = ((const uint4*)vp)[i];
        __half h8[8];
        *(uint4*)h8 = v;
#pragma unroll
        for (int t = 0; t < 8; t++) Vt[(d0 + t) * 72 + j] = h8[t];
    }
    for (int i = tid; i < 169; i += 128) biasH[i] = rbt[i * 8 + h];
    if (tid < 49) {
        int iy = tid / 7, ix = tid - iy * 7;
        int wy = (win >> 3) & 7, wx = win & 7;
        int y = wy * 7 + iy, x = wx * 7 + ix;
        int ry = y < 49 ? 0 : (y < 53 ? 1 : 2);
        int rx = x < 49 ? 0 : (x < 53 ? 1 : 2);
        cnt[tid] = ry * 3 + rx;
    }
    __syncthreads();

    const int r0 = warp * 16 + g;
    float invs[2];

    int cjy[7][2], cjx[7][2];
#pragma unroll
    for (int na = 0; na < 7; na++)
#pragma unroll
        for (int e = 0; e < 2; e++) {
            int col = na * 8 + 2 * tg + e;
            cjy[na][e] = (col < 49) ? col / 7 : -1;
            cjx[na][e] = col - cjy[na][e] * 7;
        }

    // ---- S = Q K^T (fp16 k16), fused bias+mask+exp+rowsum ----
    {
        float acc[7][4];
#pragma unroll
        for (int na = 0; na < 7; na++)
#pragma unroll
            for (int l = 0; l < 4; l++) acc[na][l] = 0.f;

#pragma unroll
        for (int ka = 0; ka < 2; ka++) {           // k = 32 halves
            const int kw = ka * 8;
            unsigned a[4];
            a[0] = Qs[r0 * 20 + kw + tg];
            a[1] = Qs[(r0 + 8) * 20 + kw + tg];
            a[2] = Qs[r0 * 20 + kw + tg + 4];
            a[3] = Qs[(r0 + 8) * 20 + kw + tg + 4];
#pragma unroll
            for (int na = 0; na < 7; na++) {
                int nr = na * 8 + g;
                unsigned b[2] = { Ks[nr * 20 + kw + tg],
                                  Ks[nr * 20 + kw + tg + 4] };
                mma16(acc[na], a, b);
            }
        }

#pragma unroll
        for (int half = 0; half < 2; half++) {
            int row = r0 + half * 8;
            bool rok = row < 49;
            int iy = 0, ix = 0, ci = 0;
            if (rok) { iy = row / 7; ix = row - iy * 7; ci = cnt[row]; }
            float esum = 0.f;
#pragma unroll
            for (int na = 0; na < 7; na++) {
                float ev0 = 0.f, ev1 = 0.f;
#pragma unroll
                for (int e = 0; e < 2; e++) {
                    int col = na * 8 + 2 * tg + e;
                    if (rok && cjy[na][e] >= 0) {
                        float v = acc[na][half * 2 + e]
                                + biasH[(iy - cjy[na][e] + 6) * 13
                                        + (ix - cjx[na][e] + 6)];
                        if (cnt[col] != ci) v -= 100.f;
                        float ev = __expf(v);
                        if (e == 0) ev0 = ev; else ev1 = ev;
                    }
                }
                half2 p = __floats2half2_rn(ev0, ev1);
                Pw[row * 36 + na * 4 + tg] = *(unsigned*)&p;
                esum += ev0 + ev1;
            }
            Pw[row * 36 + 28 + tg] = 0u;           // cols 56-63 zero
            esum += __shfl_xor_sync(0xffffffffu, esum, 1);
            esum += __shfl_xor_sync(0xffffffffu, esum, 2);
            invs[half] = 1.f / esum;
        }
    }
    __syncwarp();   // each warp produces and consumes its own 16 P-rows

    // ---- O = P V (fp16 k16, k = 64 tokens incl. zero pad) ----
    {
        float o[4][4];
#pragma unroll
        for (int na = 0; na < 4; na++)
#pragma unroll
            for (int l = 0; l < 4; l++) o[na][l] = 0.f;

        const unsigned* VtW = (const unsigned*)Vt;
#pragma unroll
        for (int ka = 0; ka < 4; ka++) {
            const int kw = ka * 8;
            unsigned a[4];
            a[0] = Pw[r0 * 36 + kw + tg];
            a[1] = Pw[(r0 + 8) * 36 + kw + tg];
            a[2] = Pw[r0 * 36 + kw + tg + 4];
            a[3] = Pw[(r0 + 8) * 36 + kw + tg + 4];
#pragma unroll
            for (int na = 0; na < 4; na++) {
                int dr = na * 8 + g;
                unsigned b[2] = { VtW[dr * 36 + kw + tg],
                                  VtW[dr * 36 + kw + tg + 4] };
                mma16(o[na], a, b);
            }
        }

#pragma unroll
        for (int half = 0; half < 2; half++) {
            int row = r0 + half * 8;
            if (row < 49) {
                float s = invs[half];
                __half* op = g_aoh + (win * 49 + row) * 256 + h * 32;
#pragma unroll
                for (int na = 0; na < 4; na++) {
                    int col = na * 8 + 2 * tg;
                    *(half2*)(op + col) =
                        __floats2half2_rn(o[na][half * 2 + 0] * s,
                                          o[na][half * 2 + 1] * s);
                }
            }
        }
    }
}

// ============================================================
extern "C" void kernel_launch(void* const* d_in, const int* in_sizes, int n_in,
                              void* d_out, int out_size)
{
    const float* query  = (const float*)d_in[0];
    const float* w_qkv  = (const float*)d_in[1];
    const float* b_qkv  = (const float*)d_in[2];
    const float* w_proj = (const float*)d_in[3];
    const float* b_proj = (const float*)d_in[4];
    const float* rbt    = (const float*)d_in[5];
    float* out = (float*)d_out;

    static int attr_done = 0;
    if (!attr_done) {
        cudaFuncSetAttribute(hgemm<0>,
            cudaFuncAttributeMaxDynamicSharedMemorySize, SMEM_BYTES);
        cudaFuncSetAttribute(hgemm<1>,
            cudaFuncAttributeMaxDynamicSharedMemorySize, SMEM_BYTES);
        attr_done = 1;
    }

    conv_q<<<12544, 256>>>((const float4*)query);
    conv_w<<<1024, 256>>>(w_qkv, w_proj);

    dim3 g1(392, 6);
    hgemm<0><<<g1, 256, SMEM_BYTES>>>(b_qkv, nullptr);

    attn_kernel<<<8192, 128>>>(rbt);

    dim3 g3(392, 2);
    hgemm<1><<<g3, 256, SMEM_BYTES>>>(b_proj, out);
}